// round 16
// baseline (speedup 1.0000x reference)
#include <cuda_runtime.h>
#include <math.h>

#define BS 2
#define SN 512
#define W 64
#define MODES 16
#define PAIRS ((SN*(SN-1))/2)
#define GRID 296
#define NTHR 512

// ---------------- scratch (device globals; no allocation) ----------------
__device__ float g_h [BS*W*SN];
__device__ float g_hT[BS*SN*W];
__device__ float g_a [BS*W*SN];
__device__ float g_aT[BS*SN*W];
__device__ float g_p [BS*W*SN];
__device__ float g_pT[BS*SN*W];
__device__ float g_ux[BS*SN*SN];   // exp(-|p_i - p_j|)
__device__ float g_vr[BS*SN*SN];   // |a_i - a_j|
__device__ float g_Xf[BS*W*MODES*2];
__device__ int   g_vrmax[4*BS];
__device__ float g_cos[SN*MODES];
__device__ float g_sin[SN*MODES];

// ---------------- grid-wide barrier (atomic busy spin — proven fastest) ----
__device__ int          g_count = 0;
__device__ volatile int g_gen   = 0;

__device__ __forceinline__ void gbar() {
    __syncthreads();
    if (threadIdx.x == 0) {
        __threadfence();
        int my = g_gen;
        if (atomicAdd(&g_count, 1) == GRID - 1) {
            g_count = 0;
            __threadfence();
            g_gen = my + 1;
        } else {
            while (g_gen == my) { }
        }
        __threadfence();
    }
    __syncthreads();
}

// ---- 64x64 distance tile via SYRK trick, 512 threads, 8 outputs/thread ----
// MODE 0: dst = exp(-d)   MODE 1: dst = d, track per-(l,b) max
template<int MODE>
__device__ __forceinline__ void dist_tile(const float* __restrict__ src,
                                          float* __restrict__ dst,
                                          int b, int tile, float* sb, int l) {
    float* sI = sb;
    float* sJ = sb + 4096;
    float* nI = sb + 8192;
    float* nJ = sb + 8256;
    int* smax = (int*)(sb + 8320);
    const int tid = threadIdx.x;
    const int I0 = (tile >> 3) << 6, J0 = (tile & 7) << 6;

    for (int e = tid; e < 1024; e += NTHR) {
        int c = e >> 4, q = e & 15;
        ((float4*)sI)[c*16 + q] = *(const float4*)(src + (b*W + c)*SN + I0 + q*4);
        ((float4*)sJ)[c*16 + q] = *(const float4*)(src + (b*W + c)*SN + J0 + q*4);
    }
    if (MODE == 1 && tid == 0) *smax = 0;
    __syncthreads();
    if (tid < 64) {
        float s = 0.f;
        #pragma unroll 16
        for (int c = 0; c < W; c++) { float v = sI[c*64 + tid]; s += v*v; }
        nI[tid] = s;
    } else if (tid < 128) {
        int t = tid - 64;
        float s = 0.f;
        #pragma unroll 16
        for (int c = 0; c < W; c++) { float v = sJ[c*64 + t]; s += v*v; }
        nJ[t] = s;
    }
    __syncthreads();

    const int tx = tid & 15, ty = tid >> 4;   // ty in 0..31; rows ty, ty+32
    float acc[2][4] = {};
    #pragma unroll 4
    for (int c = 0; c < W; c++) {
        float r0 = sI[c*64 + ty];
        float r1 = sI[c*64 + ty + 32];
        float4 rj = *(const float4*)(sJ + c*64 + tx*4);
        float rjv[4] = {rj.x, rj.y, rj.z, rj.w};
        #pragma unroll
        for (int s = 0; s < 4; s++) {
            acc[0][s] += r0 * rjv[s];
            acc[1][s] += r1 * rjv[s];
        }
    }

    float vmax = 0.f;
    #pragma unroll
    for (int r = 0; r < 2; r++) {
        int row = ty + 32*r;
        float nr = nI[row];
        float ov[4];
        #pragma unroll
        for (int s = 0; s < 4; s++) {
            float d2 = nr + nJ[tx*4 + s] - 2.f*acc[r][s];
            float d = sqrtf(fmaxf(d2, 0.f));
            if (MODE == 0) ov[s] = expf(-d);
            else { ov[s] = d; vmax = fmaxf(vmax, d); }
        }
        *(float4*)(dst + ((size_t)b*SN + I0 + row)*SN + J0 + tx*4) =
            make_float4(ov[0], ov[1], ov[2], ov[3]);
    }
    if (MODE == 1) {
        #pragma unroll
        for (int o2 = 16; o2; o2 >>= 1)
            vmax = fmaxf(vmax, __shfl_down_sync(0xffffffffu, vmax, o2));
        if ((tid & 31) == 0) atomicMax(smax, __float_as_int(vmax));
        __syncthreads();
        if (tid == 0) atomicMax(&g_vrmax[l*BS + b], *smax);
    }
    __syncthreads();
}

extern "C" __global__ void __launch_bounds__(NTHR, 2)
mega(const float* __restrict__ x, const float* __restrict__ vecs,
     const float* __restrict__ fc0_w, const float* __restrict__ fc0_b,
     const float* __restrict__ spec_w, const float* __restrict__ conv_w,
     const float* __restrict__ conv_b, const float* __restrict__ fc1_w,
     const float* __restrict__ fc1_b, const float* __restrict__ fc2_w,
     const float* __restrict__ fc2_b, float* __restrict__ out)
{
    __shared__ __align__(16) float sb[8448];   // 33.8 KB, aliased per phase
    const int tid  = threadIdx.x;
    const int lane = tid & 31;
    const int wp   = tid >> 5;                 // 16 warps

    // ================= phase 0: trig tables, vrmax reset, fc0 =================
    for (int t = blockIdx.x*NTHR + tid; t < SN*MODES; t += GRID*NTHR) {
        int j = t >> 4, k = t & 15;
        int ph = (j * k) & (SN - 1);
        double ang = (double)ph * (6.283185307179586476925286766559 / (double)SN);
        g_cos[t] = (float)cos(ang);
        g_sin[t] = (float)sin(ang);
    }
    for (int t = blockIdx.x*NTHR + tid; t < 4*BS; t += GRID*NTHR) g_vrmax[t] = 0;
    for (int e = blockIdx.x*NTHR + tid; e < BS*W*SN; e += GRID*NTHR) {
        int bb = e / (W*SN);
        int r  = e - bb*(W*SN);
        int c  = r >> 9;
        int j  = r & (SN-1);
        float x0 = x[(bb*SN + j)*2 + 0];
        float x1 = x[(bb*SN + j)*2 + 1];
        g_h[e] = x0*fc0_w[c] + x1*fc0_w[W + c] + fc0_b[c];
    }
    gbar();

    for (int l = 0; l < 4; l++) {
        // ===== Phase A: DFT (0..127) + 1x1 conv (128..255) =====
        for (int task = blockIdx.x; task < 256; task += GRID) {
            if (task < 128) {
                int bc = task;
                sb[tid] = g_h[bc*SN + tid];      // 512 elems, 1/thread
                __syncthreads();
                int m0 = wp;                      // 16 warps = 16 modes
                float re0 = 0.f, im0 = 0.f;
                for (int j = lane; j < SN; j += 32) {
                    float hv = sb[j];
                    re0 += hv * g_cos[j*MODES + m0];
                    im0 -= hv * g_sin[j*MODES + m0];
                }
                #pragma unroll
                for (int o = 16; o; o >>= 1) {
                    re0 += __shfl_down_sync(0xffffffffu, re0, o);
                    im0 += __shfl_down_sync(0xffffffffu, im0, o);
                }
                if (lane == 0) {
                    g_Xf[(bc*MODES + m0)*2 + 0] = re0;
                    g_Xf[(bc*MODES + m0)*2 + 1] = im0;
                }
                __syncthreads();
            } else {
                int t2 = task - 128;
                int b = t2 >> 6, o = t2 & 63;
                if (tid < W) sb[tid] = conv_w[((size_t)l*W + o)*W + tid];
                __syncthreads();
                int j = tid;                      // one j per thread
                float acc = conv_b[l*W + o];
                #pragma unroll 16
                for (int c = 0; c < W; c++) acc += sb[c] * g_h[(b*W + c)*SN + j];
                g_p [(b*W + o)*SN + j] = acc;
                g_pT[((size_t)b*SN + j)*W + o] = acc;
                __syncthreads();
            }
        }
        gbar();

        // ===== Phase B: mix+synth only (128 tasks) =====
        {
            const float2* wl2 = (const float2*)(spec_w + (size_t)l*W*W*MODES*2);
            for (int task = blockIdx.x; task < 128; task += GRID) {
                int b = task >> 6, o = task & 63;
                if (tid < W*MODES*2) sb[tid] = g_Xf[b*W*MODES*2 + tid];  // 2048
                if (tid + 512  < W*MODES*2) sb[tid + 512]  = g_Xf[b*W*MODES*2 + tid + 512];
                if (tid + 1024 < W*MODES*2) sb[tid + 1024] = g_Xf[b*W*MODES*2 + tid + 1024];
                if (tid + 1536 < W*MODES*2) sb[tid + 1536] = g_Xf[b*W*MODES*2 + tid + 1536];
                __syncthreads();
                int k0 = wp;                       // 16 warps = 16 modes
                float yr0 = 0.f, yi0 = 0.f;
                for (int i = lane; i < W; i += 32) {
                    float2 w0 = wl2[(i*W + o)*MODES + k0];
                    float xr0 = sb[(i*MODES + k0)*2], xi0 = sb[(i*MODES + k0)*2 + 1];
                    yr0 += xr0*w0.x - xi0*w0.y;
                    yi0 += xr0*w0.y + xi0*w0.x;
                }
                #pragma unroll
                for (int o2 = 16; o2; o2 >>= 1) {
                    yr0 += __shfl_down_sync(0xffffffffu, yr0, o2);
                    yi0 += __shfl_down_sync(0xffffffffu, yi0, o2);
                }
                if (lane == 0) {
                    sb[2048 + k0*2]     = yr0;
                    sb[2048 + k0*2 + 1] = yi0;
                }
                __syncthreads();
                int j = tid;                       // one j per thread
                float acc = sb[2048];
                #pragma unroll
                for (int k = 1; k < MODES; k++)
                    acc += 2.f*(sb[2048 + 2*k]*g_cos[j*MODES + k]
                              - sb[2048 + 2*k + 1]*g_sin[j*MODES + k]);
                float a = acc * (1.0f/(float)SN);
                g_a [(b*W + o)*SN + j] = a;
                g_aT[((size_t)b*SN + j)*W + o] = a;
                __syncthreads();
            }
        }
        gbar();

        // ===== Phase C: ux tiles (0..127, from p) + vr tiles (128..255, from a) =====
        for (int task = blockIdx.x; task < 256; task += GRID) {
            if (task < 128)
                dist_tile<0>(g_p, g_ux, task >> 6, task & 63, sb, l);
            else {
                int t2 = task - 128;
                dist_tile<1>(g_a, g_vr, t2 >> 6, t2 & 63, sb, l);
            }
        }
        gbar();

        // ===== Phase D: quad-column collide (256 tasks, 4 columns/block) =====
        {
            int*   s_idx = (int*)sb;              // 2048 (4 grp x 512)
            int*   s_pid = (int*)sb + 2048;       // 2048
            float* s_wt  = sb + 4096;             // 2048
            float* sMx   = sb + 6144;             // 512
            float* sMv   = sb + 6656;             // 512
            float* sRc   = sb + 7168;             // 256
            int*   s_cnt = (int*)(sb + 7424);     // 16
            int relu = (l < 3);
            const int grp  = tid >> 7;            // 0..3
            const int gtid = tid & 127;
            const int gwp  = (tid >> 5) & 3;      // warp within group
            const int barid = 1 + grp;
            for (int task = blockIdx.x; task < (BS*SN)/4; task += GRID) {
                int b = task >> 7;
                int j = ((task & 127) << 2) + grp;
                float thr = 0.1f * __int_as_float(g_vrmax[l*BS + b]);
                const float* vrrow = g_vr + ((size_t)b*SN + j)*SN;
                const float* uxrow = g_ux + ((size_t)b*SN + j)*SN;

                // warp-local compaction: warp gwp owns i in [gwp*128, gwp*128+128)
                int cl = 0;
                #pragma unroll
                for (int it = 0; it < 4; it++) {
                    int i = gwp*128 + it*32 + lane;
                    float vr = vrrow[i];
                    bool pred = (vr * uxrow[i]) > thr;
                    unsigned m = __ballot_sync(0xffffffffu, pred);
                    if (pred) {
                        int pos = grp*512 + gwp*128 + cl + __popc(m & ((1u << lane) - 1u));
                        int lo = i < j ? i : j, hi = i < j ? j : i;
                        s_idx[pos] = i;
                        s_pid[pos] = lo*SN - (lo*(lo+1))/2 + hi - lo - 1;
                        s_wt [pos] = (i < j) ? vr : -vr;
                    }
                    cl += __popc(m);
                }
                if (lane == 0) s_cnt[grp*4 + gwp] = cl;
                asm volatile("bar.sync %0, 128;" :: "r"(barid) : "memory");

                int c0 = s_cnt[grp*4 + 0], c1 = s_cnt[grp*4 + 1];
                int c2 = s_cnt[grp*4 + 2], c3 = s_cnt[grp*4 + 3];
                int o1 = c0, o2s = o1 + c1, o3 = o2s + c2;
                int n  = o3 + c3;

                // --- Mx/Mv: c-major (coalesced, L2-resident) ---
                int c = gtid & 63, half = gtid >> 6;
                float mx = 0.f, mv = 0.f;
                const float* pTb = g_pT + (size_t)b*SN*W + c;
                const float* aTb = g_aT + (size_t)b*SN*W + c;
                #pragma unroll
                for (int seg = 0; seg < 4; seg++) {
                    int ns = s_cnt[grp*4 + seg];
                    for (int k = half; k < ns; k += 2) {
                        int i = s_idx[grp*512 + seg*128 + k];
                        mx += pTb[(size_t)i*W];
                        mv += aTb[(size_t)i*W];
                    }
                }
                sMx[grp*128 + gtid] = mx;
                sMv[grp*128 + gtid] = mv;

                // --- vecs projection: lanes sweep concatenated entries; 2 passes x 8 ch ---
                #pragma unroll
                for (int pass = 0; pass < 2; pass++) {
                    const float* vbase = vecs + (((size_t)l*BS + b)*W
                                       + pass*32 + gwp*8)*(size_t)PAIRS;
                    float a0=0.f,a1=0.f,a2=0.f,a3=0.f,a4=0.f,a5=0.f,a6=0.f,a7=0.f;
                    for (int k0 = 0; k0 < n; k0 += 32) {
                        int k = k0 + lane;
                        bool act = k < n;
                        int kk = act ? k : 0;
                        int base = (kk < o1)  ? kk
                                 : (kk < o2s) ? 128 + (kk - o1)
                                 : (kk < o3)  ? 256 + (kk - o2s)
                                 :              384 + (kk - o3);
                        base += grp*512;
                        int   pid = s_pid[base];
                        float wt  = act ? s_wt[base] : 0.f;
                        a0 += wt * vbase[pid];
                        a1 += wt * vbase[(size_t)1*PAIRS + pid];
                        a2 += wt * vbase[(size_t)2*PAIRS + pid];
                        a3 += wt * vbase[(size_t)3*PAIRS + pid];
                        a4 += wt * vbase[(size_t)4*PAIRS + pid];
                        a5 += wt * vbase[(size_t)5*PAIRS + pid];
                        a6 += wt * vbase[(size_t)6*PAIRS + pid];
                        a7 += wt * vbase[(size_t)7*PAIRS + pid];
                    }
                    #pragma unroll
                    for (int o2r = 16; o2r; o2r >>= 1) {
                        a0 += __shfl_down_sync(0xffffffffu, a0, o2r);
                        a1 += __shfl_down_sync(0xffffffffu, a1, o2r);
                        a2 += __shfl_down_sync(0xffffffffu, a2, o2r);
                        a3 += __shfl_down_sync(0xffffffffu, a3, o2r);
                        a4 += __shfl_down_sync(0xffffffffu, a4, o2r);
                        a5 += __shfl_down_sync(0xffffffffu, a5, o2r);
                        a6 += __shfl_down_sync(0xffffffffu, a6, o2r);
                        a7 += __shfl_down_sync(0xffffffffu, a7, o2r);
                    }
                    if (lane == 0) {
                        int rb = grp*64 + pass*32 + gwp*8;
                        sRc[rb + 0] = a0; sRc[rb + 1] = a1;
                        sRc[rb + 2] = a2; sRc[rb + 3] = a3;
                        sRc[rb + 4] = a4; sRc[rb + 5] = a5;
                        sRc[rb + 6] = a6; sRc[rb + 7] = a7;
                    }
                }
                asm volatile("bar.sync %0, 128;" :: "r"(barid) : "memory");

                if (gtid < W) {
                    float Mx = sMx[grp*128 + gtid] + sMx[grp*128 + gtid + 64];
                    float Mv = sMv[grp*128 + gtid] + sMv[grp*128 + gtid + 64];
                    float R  = sRc[grp*64 + gtid];
                    float Sc = (float)n;
                    float aj = g_aT[((size_t)b*SN + j)*W + gtid];
                    float pj = g_pT[((size_t)b*SN + j)*W + gtid];
                    float vnew = aj + 0.5f*aj*Sc - 0.5f*Mv + R;
                    float C = Sc + 1.0f;
                    float xnew = (Mx + pj + pj*C) / (2.0f*C);
                    float h = xnew + vnew;
                    if (relu) h = fmaxf(h, 0.0f);
                    g_h [(b*W + gtid)*SN + j] = h;
                    g_hT[((size_t)b*SN + j)*W + gtid] = h;
                }
                asm volatile("bar.sync %0, 128;" :: "r"(barid) : "memory");
            }
        }
        gbar();
    }

    // ================= head: 4 rows per task (256 tasks) =================
    for (int task = blockIdx.x; task < 256; task += GRID) {
        int b = task >> 7, sp = task & 127;
        int q = tid >> 7, m = tid & 127;       // 4 row-groups of 128 threads
        int s = sp*4 + q;
        __syncthreads();
        if (tid < 256) {
            int qq = tid >> 6, i = tid & 63;
            sb[tid] = g_hT[((size_t)b*SN + (sp*4 + qq))*W + i];
        }
        __syncthreads();
        float acc = fc1_b[m];
        #pragma unroll 16
        for (int cc = 0; cc < W; cc++) acc += sb[q*64 + cc] * fc1_w[cc*128 + m];
        acc = fmaxf(acc, 0.0f) * fc2_w[m];
        sb[256 + tid] = acc;
        __syncthreads();
        #pragma unroll
        for (int o2 = 64; o2; o2 >>= 1) {
            if (m < o2) sb[256 + q*128 + m] += sb[256 + q*128 + m + o2];
            __syncthreads();
        }
        if (m == 0) out[b*SN + s] = sb[256 + q*128] + fc2_b[0];
    }
}

// ---------------- launch ----------------
extern "C" void kernel_launch(void* const* d_in, const int* in_sizes, int n_in,
                              void* d_out, int out_size) {
    const float* x      = (const float*)d_in[0];
    const float* vecs   = (const float*)d_in[2];
    const float* fc0_w  = (const float*)d_in[3];
    const float* fc0_b  = (const float*)d_in[4];
    const float* spec_w = (const float*)d_in[5];
    const float* conv_w = (const float*)d_in[6];
    const float* conv_b = (const float*)d_in[7];
    const float* fc1_w  = (const float*)d_in[8];
    const float* fc1_b  = (const float*)d_in[9];
    const float* fc2_w  = (const float*)d_in[10];
    const float* fc2_b  = (const float*)d_in[11];
    float* out = (float*)d_out;

    mega<<<GRID, NTHR>>>(x, vecs, fc0_w, fc0_b, spec_w, conv_w, conv_b,
                         fc1_w, fc1_b, fc2_w, fc2_b, out);
}

// round 17
// speedup vs baseline: 1.1379x; 1.1379x over previous
#include <cuda_runtime.h>
#include <math.h>

#define BS 2
#define SN 512
#define W 64
#define MODES 16
#define PAIRS ((SN*(SN-1))/2)
#define GRID 296
#define NTHR 512

// ---------------- scratch (device globals; no allocation) ----------------
__device__ float g_h [BS*W*SN];
__device__ float g_hT[BS*SN*W];
__device__ float g_a [BS*W*SN];
__device__ float g_aT[BS*SN*W];
__device__ float g_p [BS*W*SN];
__device__ float g_pT[BS*SN*W];
__device__ float g_ux[BS*SN*SN];   // exp(-|p_i - p_j|)
__device__ float g_vr[BS*SN*SN];   // |a_i - a_j|
__device__ float g_Xf[BS*W*MODES*2];
__device__ int   g_vrmax[4*BS];
__device__ float g_cos[SN*MODES];
__device__ float g_sin[SN*MODES];

// ---------------- grid-wide barrier (atomic busy spin — proven fastest) ----
__device__ int          g_count = 0;
__device__ volatile int g_gen   = 0;

__device__ __forceinline__ void gbar() {
    __syncthreads();
    if (threadIdx.x == 0) {
        __threadfence();
        int my = g_gen;
        if (atomicAdd(&g_count, 1) == GRID - 1) {
            g_count = 0;
            __threadfence();
            g_gen = my + 1;
        } else {
            while (g_gen == my) { }
        }
        __threadfence();
    }
    __syncthreads();
}

// ---- 64x64 distance tile via SYRK trick, 512 threads, 8 outputs/thread ----
// MODE 0: dst = exp(-d)   MODE 1: dst = d, track per-(l,b) max
template<int MODE>
__device__ __forceinline__ void dist_tile(const float* __restrict__ src,
                                          float* __restrict__ dst,
                                          int b, int tile, float* sb, int l) {
    float* sI = sb;
    float* sJ = sb + 4096;
    float* nI = sb + 8192;
    float* nJ = sb + 8256;
    int* smax = (int*)(sb + 8320);
    const int tid = threadIdx.x;
    const int I0 = (tile >> 3) << 6, J0 = (tile & 7) << 6;

    for (int e = tid; e < 1024; e += NTHR) {
        int c = e >> 4, q = e & 15;
        ((float4*)sI)[c*16 + q] = *(const float4*)(src + (b*W + c)*SN + I0 + q*4);
        ((float4*)sJ)[c*16 + q] = *(const float4*)(src + (b*W + c)*SN + J0 + q*4);
    }
    if (MODE == 1 && tid == 0) *smax = 0;
    __syncthreads();
    if (tid < 64) {
        float s = 0.f;
        #pragma unroll 16
        for (int c = 0; c < W; c++) { float v = sI[c*64 + tid]; s += v*v; }
        nI[tid] = s;
    } else if (tid < 128) {
        int t = tid - 64;
        float s = 0.f;
        #pragma unroll 16
        for (int c = 0; c < W; c++) { float v = sJ[c*64 + t]; s += v*v; }
        nJ[t] = s;
    }
    __syncthreads();

    const int tx = tid & 15, ty = tid >> 4;   // ty in 0..31; rows ty, ty+32
    float acc[2][4] = {};
    #pragma unroll 4
    for (int c = 0; c < W; c++) {
        float r0 = sI[c*64 + ty];
        float r1 = sI[c*64 + ty + 32];
        float4 rj = *(const float4*)(sJ + c*64 + tx*4);
        float rjv[4] = {rj.x, rj.y, rj.z, rj.w};
        #pragma unroll
        for (int s = 0; s < 4; s++) {
            acc[0][s] += r0 * rjv[s];
            acc[1][s] += r1 * rjv[s];
        }
    }

    float vmax = 0.f;
    #pragma unroll
    for (int r = 0; r < 2; r++) {
        int row = ty + 32*r;
        float nr = nI[row];
        float ov[4];
        #pragma unroll
        for (int s = 0; s < 4; s++) {
            float d2 = nr + nJ[tx*4 + s] - 2.f*acc[r][s];
            float d = sqrtf(fmaxf(d2, 0.f));
            if (MODE == 0) ov[s] = expf(-d);
            else { ov[s] = d; vmax = fmaxf(vmax, d); }
        }
        *(float4*)(dst + ((size_t)b*SN + I0 + row)*SN + J0 + tx*4) =
            make_float4(ov[0], ov[1], ov[2], ov[3]);
    }
    if (MODE == 1) {
        #pragma unroll
        for (int o2 = 16; o2; o2 >>= 1)
            vmax = fmaxf(vmax, __shfl_down_sync(0xffffffffu, vmax, o2));
        if ((tid & 31) == 0) atomicMax(smax, __float_as_int(vmax));
        __syncthreads();
        if (tid == 0) atomicMax(&g_vrmax[l*BS + b], *smax);
    }
    __syncthreads();
}

extern "C" __global__ void __launch_bounds__(NTHR, 2)
mega(const float* __restrict__ x, const float* __restrict__ vecs,
     const float* __restrict__ fc0_w, const float* __restrict__ fc0_b,
     const float* __restrict__ spec_w, const float* __restrict__ conv_w,
     const float* __restrict__ conv_b, const float* __restrict__ fc1_w,
     const float* __restrict__ fc1_b, const float* __restrict__ fc2_w,
     const float* __restrict__ fc2_b, float* __restrict__ out)
{
    __shared__ __align__(16) float sb[8448];   // 33.8 KB, aliased per phase
    const int tid  = threadIdx.x;
    const int lane = tid & 31;
    const int wp   = tid >> 5;                 // 16 warps

    // ================= phase 0: trig tables, vrmax reset, fc0 =================
    for (int t = blockIdx.x*NTHR + tid; t < SN*MODES; t += GRID*NTHR) {
        int j = t >> 4, k = t & 15;
        int ph = (j * k) & (SN - 1);
        double ang = (double)ph * (6.283185307179586476925286766559 / (double)SN);
        g_cos[t] = (float)cos(ang);
        g_sin[t] = (float)sin(ang);
    }
    for (int t = blockIdx.x*NTHR + tid; t < 4*BS; t += GRID*NTHR) g_vrmax[t] = 0;
    for (int e = blockIdx.x*NTHR + tid; e < BS*W*SN; e += GRID*NTHR) {
        int bb = e / (W*SN);
        int r  = e - bb*(W*SN);
        int c  = r >> 9;
        int j  = r & (SN-1);
        float x0 = x[(bb*SN + j)*2 + 0];
        float x1 = x[(bb*SN + j)*2 + 1];
        g_h[e] = x0*fc0_w[c] + x1*fc0_w[W + c] + fc0_b[c];
    }
    gbar();

    for (int l = 0; l < 4; l++) {
        // ===== Phase A: DFT (0..127) + 1x1 conv (128..255) =====
        for (int task = blockIdx.x; task < 256; task += GRID) {
            if (task < 128) {
                int bc = task;
                sb[tid] = g_h[bc*SN + tid];      // 512 elems, 1/thread
                __syncthreads();
                int m0 = wp;                      // 16 warps = 16 modes
                float re0 = 0.f, im0 = 0.f;
                for (int j = lane; j < SN; j += 32) {
                    float hv = sb[j];
                    re0 += hv * g_cos[j*MODES + m0];
                    im0 -= hv * g_sin[j*MODES + m0];
                }
                #pragma unroll
                for (int o = 16; o; o >>= 1) {
                    re0 += __shfl_down_sync(0xffffffffu, re0, o);
                    im0 += __shfl_down_sync(0xffffffffu, im0, o);
                }
                if (lane == 0) {
                    g_Xf[(bc*MODES + m0)*2 + 0] = re0;
                    g_Xf[(bc*MODES + m0)*2 + 1] = im0;
                }
                __syncthreads();
            } else {
                int t2 = task - 128;
                int b = t2 >> 6, o = t2 & 63;
                if (tid < W) sb[tid] = conv_w[((size_t)l*W + o)*W + tid];
                __syncthreads();
                int j = tid;                      // one j per thread
                float acc = conv_b[l*W + o];
                #pragma unroll 16
                for (int c = 0; c < W; c++) acc += sb[c] * g_h[(b*W + c)*SN + j];
                g_p [(b*W + o)*SN + j] = acc;
                g_pT[((size_t)b*SN + j)*W + o] = acc;
                __syncthreads();
            }
        }
        gbar();

        // ===== Phase B: mix+synth only (128 tasks) =====
        {
            const float2* wl2 = (const float2*)(spec_w + (size_t)l*W*W*MODES*2);
            for (int task = blockIdx.x; task < 128; task += GRID) {
                int b = task >> 6, o = task & 63;
                if (tid < W*MODES*2) sb[tid] = g_Xf[b*W*MODES*2 + tid];  // 2048
                if (tid + 512  < W*MODES*2) sb[tid + 512]  = g_Xf[b*W*MODES*2 + tid + 512];
                if (tid + 1024 < W*MODES*2) sb[tid + 1024] = g_Xf[b*W*MODES*2 + tid + 1024];
                if (tid + 1536 < W*MODES*2) sb[tid + 1536] = g_Xf[b*W*MODES*2 + tid + 1536];
                __syncthreads();
                int k0 = wp;                       // 16 warps = 16 modes
                float yr0 = 0.f, yi0 = 0.f;
                for (int i = lane; i < W; i += 32) {
                    float2 w0 = wl2[(i*W + o)*MODES + k0];
                    float xr0 = sb[(i*MODES + k0)*2], xi0 = sb[(i*MODES + k0)*2 + 1];
                    yr0 += xr0*w0.x - xi0*w0.y;
                    yi0 += xr0*w0.y + xi0*w0.x;
                }
                #pragma unroll
                for (int o2 = 16; o2; o2 >>= 1) {
                    yr0 += __shfl_down_sync(0xffffffffu, yr0, o2);
                    yi0 += __shfl_down_sync(0xffffffffu, yi0, o2);
                }
                if (lane == 0) {
                    sb[2048 + k0*2]     = yr0;
                    sb[2048 + k0*2 + 1] = yi0;
                }
                __syncthreads();
                int j = tid;                       // one j per thread
                float acc = sb[2048];
                #pragma unroll
                for (int k = 1; k < MODES; k++)
                    acc += 2.f*(sb[2048 + 2*k]*g_cos[j*MODES + k]
                              - sb[2048 + 2*k + 1]*g_sin[j*MODES + k]);
                float a = acc * (1.0f/(float)SN);
                g_a [(b*W + o)*SN + j] = a;
                g_aT[((size_t)b*SN + j)*W + o] = a;
                __syncthreads();
            }
        }
        gbar();

        // ===== Phase C: ux tiles (0..127, from p) + vr tiles (128..255, from a) =====
        for (int task = blockIdx.x; task < 256; task += GRID) {
            if (task < 128)
                dist_tile<0>(g_p, g_ux, task >> 6, task & 63, sb, l);
            else {
                int t2 = task - 128;
                dist_tile<1>(g_a, g_vr, t2 >> 6, t2 & 63, sb, l);
            }
        }
        gbar();

        // ===== Phase D: dual-column collide (512 tasks, 2 cols/block, 256 thr each) =====
        {
            int*   s_idx = (int*)sb;              // 1024 (2 grp x 512) segmented
            int*   s_pid = (int*)sb + 1024;       // 1024 segmented
            float* s_wt  = sb + 2048;             // 1024 segmented
            int*   d_idx = (int*)sb + 3072;       // 1024 contiguous
            int*   d_pid = (int*)sb + 4096;       // 1024 contiguous
            float* d_wt  = sb + 5120;             // 1024 contiguous
            float* sMx   = sb + 6144;             // 512
            float* sMv   = sb + 6656;             // 512
            float* sRc   = sb + 7168;             // 128
            int*   s_cnt = (int*)(sb + 7296);     // 16 counts
            int*   s_bas = (int*)(sb + 7312);     // 16 bases + 2 totals
            int relu = (l < 3);
            const int grp  = tid >> 8;             // 0..1
            const int gtid = tid & 255;
            const int gwp  = (tid >> 5) & 7;       // warp within group (0..7)
            const int barid = 1 + grp;
            for (int task = blockIdx.x; task < (BS*SN)/2; task += GRID) {
                int b = task >> 8;
                int j = ((task & 255) << 1) + grp;
                float thr = 0.1f * __int_as_float(g_vrmax[l*BS + b]);
                const float* vrrow = g_vr + ((size_t)b*SN + j)*SN;
                const float* uxrow = g_ux + ((size_t)b*SN + j)*SN;

                // warp-segmented compaction: warp gwp owns i in [gwp*64, gwp*64+64)
                int cl = 0;
                #pragma unroll
                for (int it = 0; it < 2; it++) {
                    int i = gwp*64 + it*32 + lane;
                    float vr = vrrow[i];
                    bool pred = (vr * uxrow[i]) > thr;
                    unsigned m = __ballot_sync(0xffffffffu, pred);
                    if (pred) {
                        int pos = grp*512 + gwp*64 + cl + __popc(m & ((1u << lane) - 1u));
                        int lo = i < j ? i : j, hi = i < j ? j : i;
                        s_idx[pos] = i;
                        s_pid[pos] = lo*SN - (lo*(lo+1))/2 + hi - lo - 1;
                        s_wt [pos] = (i < j) ? vr : -vr;
                    }
                    cl += __popc(m);
                }
                if (lane == 0) s_cnt[grp*8 + gwp] = cl;
                asm volatile("bar.sync %0, 256;" :: "r"(barid) : "memory");
                if (gtid == 0) {
                    int s0 = 0;
                    #pragma unroll
                    for (int q = 0; q < 8; q++) { s_bas[grp*8 + q] = s0; s0 += s_cnt[grp*8 + q]; }
                    ((int*)(sb + 7328))[grp] = s0;
                }
                asm volatile("bar.sync %0, 256;" :: "r"(barid) : "memory");
                // contiguous copy: warp gwp copies its segment
                {
                    int ns = s_cnt[grp*8 + gwp];
                    int bas = s_bas[grp*8 + gwp];
                    for (int k = lane; k < ns; k += 32) {
                        int src = grp*512 + gwp*64 + k;
                        int dst = grp*512 + bas + k;
                        d_idx[dst] = s_idx[src];
                        d_pid[dst] = s_pid[src];
                        d_wt [dst] = s_wt [src];
                    }
                }
                asm volatile("bar.sync %0, 256;" :: "r"(barid) : "memory");
                int n = ((int*)(sb + 7328))[grp];

                // --- Mx/Mv: c-major (coalesced, L2-resident), 4 k-groups ---
                int c = gtid & 63, kg = gtid >> 6;
                float mx = 0.f, mv = 0.f;
                const float* pTb = g_pT + (size_t)b*SN*W + c;
                const float* aTb = g_aT + (size_t)b*SN*W + c;
                for (int k = kg; k < n; k += 4) {
                    int i = d_idx[grp*512 + k];
                    mx += pTb[(size_t)i*W];
                    mv += aTb[(size_t)i*W];
                }
                sMx[grp*256 + gtid] = mx;
                sMv[grp*256 + gtid] = mv;

                // --- vecs projection: lanes sweep contiguous entries; warp owns 8 ch ---
                {
                    const float* vbase = vecs + (((size_t)l*BS + b)*W + gwp*8)*(size_t)PAIRS;
                    float a0=0.f,a1=0.f,a2=0.f,a3=0.f,a4=0.f,a5=0.f,a6=0.f,a7=0.f;
                    for (int k0 = 0; k0 < n; k0 += 32) {
                        int k = k0 + lane;
                        bool act = k < n;
                        int   pid = act ? d_pid[grp*512 + k] : 0;
                        float wt  = act ? d_wt [grp*512 + k] : 0.f;
                        a0 += wt * vbase[pid];
                        a1 += wt * vbase[(size_t)1*PAIRS + pid];
                        a2 += wt * vbase[(size_t)2*PAIRS + pid];
                        a3 += wt * vbase[(size_t)3*PAIRS + pid];
                        a4 += wt * vbase[(size_t)4*PAIRS + pid];
                        a5 += wt * vbase[(size_t)5*PAIRS + pid];
                        a6 += wt * vbase[(size_t)6*PAIRS + pid];
                        a7 += wt * vbase[(size_t)7*PAIRS + pid];
                    }
                    #pragma unroll
                    for (int o2 = 16; o2; o2 >>= 1) {
                        a0 += __shfl_down_sync(0xffffffffu, a0, o2);
                        a1 += __shfl_down_sync(0xffffffffu, a1, o2);
                        a2 += __shfl_down_sync(0xffffffffu, a2, o2);
                        a3 += __shfl_down_sync(0xffffffffu, a3, o2);
                        a4 += __shfl_down_sync(0xffffffffu, a4, o2);
                        a5 += __shfl_down_sync(0xffffffffu, a5, o2);
                        a6 += __shfl_down_sync(0xffffffffu, a6, o2);
                        a7 += __shfl_down_sync(0xffffffffu, a7, o2);
                    }
                    if (lane == 0) {
                        int rb = grp*64 + gwp*8;
                        sRc[rb + 0] = a0; sRc[rb + 1] = a1;
                        sRc[rb + 2] = a2; sRc[rb + 3] = a3;
                        sRc[rb + 4] = a4; sRc[rb + 5] = a5;
                        sRc[rb + 6] = a6; sRc[rb + 7] = a7;
                    }
                }
                asm volatile("bar.sync %0, 256;" :: "r"(barid) : "memory");

                if (gtid < W) {
                    float Mx = sMx[grp*256 + gtid]       + sMx[grp*256 + gtid + 64]
                             + sMx[grp*256 + gtid + 128] + sMx[grp*256 + gtid + 192];
                    float Mv = sMv[grp*256 + gtid]       + sMv[grp*256 + gtid + 64]
                             + sMv[grp*256 + gtid + 128] + sMv[grp*256 + gtid + 192];
                    float R  = sRc[grp*64 + gtid];
                    float Sc = (float)n;
                    float aj = g_aT[((size_t)b*SN + j)*W + gtid];
                    float pj = g_pT[((size_t)b*SN + j)*W + gtid];
                    float vnew = aj + 0.5f*aj*Sc - 0.5f*Mv + R;
                    float C = Sc + 1.0f;
                    float xnew = (Mx + pj + pj*C) / (2.0f*C);
                    float h = xnew + vnew;
                    if (relu) h = fmaxf(h, 0.0f);
                    g_h [(b*W + gtid)*SN + j] = h;
                    g_hT[((size_t)b*SN + j)*W + gtid] = h;
                }
                asm volatile("bar.sync %0, 256;" :: "r"(barid) : "memory");
            }
        }
        gbar();
    }

    // ================= head: 4 rows per task (256 tasks) =================
    for (int task = blockIdx.x; task < 256; task += GRID) {
        int b = task >> 7, sp = task & 127;
        int q = tid >> 7, m = tid & 127;       // 4 row-groups of 128 threads
        int s = sp*4 + q;
        __syncthreads();
        if (tid < 256) {
            int qq = tid >> 6, i = tid & 63;
            sb[tid] = g_hT[((size_t)b*SN + (sp*4 + qq))*W + i];
        }
        __syncthreads();
        float acc = fc1_b[m];
        #pragma unroll 16
        for (int cc = 0; cc < W; cc++) acc += sb[q*64 + cc] * fc1_w[cc*128 + m];
        acc = fmaxf(acc, 0.0f) * fc2_w[m];
        sb[256 + tid] = acc;
        __syncthreads();
        #pragma unroll
        for (int o2 = 64; o2; o2 >>= 1) {
            if (m < o2) sb[256 + q*128 + m] += sb[256 + q*128 + m + o2];
            __syncthreads();
        }
        if (m == 0) out[b*SN + s] = sb[256 + q*128] + fc2_b[0];
    }
}

// ---------------- launch ----------------
extern "C" void kernel_launch(void* const* d_in, const int* in_sizes, int n_in,
                              void* d_out, int out_size) {
    const float* x      = (const float*)d_in[0];
    const float* vecs   = (const float*)d_in[2];
    const float* fc0_w  = (const float*)d_in[3];
    const float* fc0_b  = (const float*)d_in[4];
    const float* spec_w = (const float*)d_in[5];
    const float* conv_w = (const float*)d_in[6];
    const float* conv_b = (const float*)d_in[7];
    const float* fc1_w  = (const float*)d_in[8];
    const float* fc1_b  = (const float*)d_in[9];
    const float* fc2_w  = (const float*)d_in[10];
    const float* fc2_b  = (const float*)d_in[11];
    float* out = (float*)d_out;

    mega<<<GRID, NTHR>>>(x, vecs, fc0_w, fc0_b, spec_w, conv_w, conv_b,
                         fc1_w, fc1_b, fc2_w, fc2_b, out);
}